// round 12
// baseline (speedup 1.0000x reference)
#include <cuda_runtime.h>
#include <cuda_bf16.h>

#define NN 50000
#define EE 800000
#define ET (EE + NN)
#define HID 128
#define GG 64
#define OUTD 10
#define SLOPE 0.2f
#define EPSB 1e-5f

// ---------------- static scratch ----------------
__device__ __align__(16) float g_h[NN * HID];
__device__ __align__(16) __nv_bfloat16 g_featb[NN * HID];
__device__ __align__(16) float g_c[NN * HID];
__device__ float g_asrc[NN * 8];
__device__ float g_adst[NN * 8];
__device__ int   g_deg[NN];
__device__ int   g_cursor[NN];
__device__ int   g_rowptr[NN + 1];
__device__ int   g_esrc[ET];
__device__ float g_sums[2 * HID];    // double-buffered BN stats
__device__ float g_sumsq[2 * HID];
__device__ float g_pooled[GG * HID];

// ---------------- CSR build ----------------
__global__ void zero_deg_kernel(int* deg, float* pooled) {
    int i = blockIdx.x * blockDim.x + threadIdx.x;
    if (i < NN) deg[i] = 0;
    if (i < GG * HID) pooled[i] = 0.f;
}

__global__ void hist_kernel(const int* __restrict__ ei, int E, int* deg) {
    int e = blockIdx.x * blockDim.x + threadIdx.x;
    if (e >= E + NN) return;
    int dst = (e < E) ? ei[E + e] : (e - E);
    atomicAdd(&deg[dst], 1);
}

// exclusive scan; writes rowptr AND seeds cursor = rowptr
__global__ void scan_kernel(const int* __restrict__ deg,
                            int* __restrict__ rowptr,
                            int* __restrict__ cursor) {
    __shared__ int s[1024];
    const int T = 1024;
    int tid = threadIdx.x;
    int chunk = (NN + T - 1) / T;
    int start = tid * chunk;
    int sum = 0;
    for (int i = 0; i < chunk; i++) {
        int idx = start + i;
        if (idx < NN) sum += deg[idx];
    }
    s[tid] = sum;
    __syncthreads();
    for (int off = 1; off < T; off <<= 1) {
        int v = (tid >= off) ? s[tid - off] : 0;
        __syncthreads();
        s[tid] += v;
        __syncthreads();
    }
    int run = (tid == 0) ? 0 : s[tid - 1];
    for (int i = 0; i < chunk; i++) {
        int idx = start + i;
        if (idx < NN) { rowptr[idx] = run; cursor[idx] = run; run += deg[idx]; }
    }
    if (tid == T - 1) rowptr[NN] = s[T - 1];
}

__global__ void scatter_kernel(const int* __restrict__ ei, int E,
                               int* __restrict__ cursor,
                               int* __restrict__ esrc) {
    int e = blockIdx.x * blockDim.x + threadIdx.x;
    if (e >= E + NN) return;
    int src, dst;
    if (e < E) { src = ei[e]; dst = ei[E + e]; }
    else       { src = e - E; dst = e - E; }
    int pos = atomicAdd(&cursor[dst], 1);
    esrc[pos] = src;
}

// ---------------- tf32 helpers ----------------
__device__ __forceinline__ unsigned f2tf32(float f) {
    unsigned u;
    asm("cvt.rna.tf32.f32 %0, %1;" : "=r"(u) : "f"(f));
    return u;
}

__device__ __forceinline__ void mma_tf32(float* d, const unsigned* a,
                                         unsigned b0, unsigned b1) {
    asm volatile(
        "mma.sync.aligned.m16n8k8.row.col.f32.tf32.tf32.f32 "
        "{%0,%1,%2,%3},{%4,%5,%6,%7},{%8,%9},{%0,%1,%2,%3};"
        : "+f"(d[0]), "+f"(d[1]), "+f"(d[2]), "+f"(d[3])
        : "r"(a[0]), "r"(a[1]), "r"(a[2]), "r"(a[3]), "r"(b0), "r"(b1));
}

// ---------------- tensor-core GEMM, fused: BN-prologue + attention epilogue ----
__global__ __launch_bounds__(256) void gemm_tc_kernel(
        float* __restrict__ A, const float* __restrict__ B,
        const float* __restrict__ bias,
        float* __restrict__ Cf32, __nv_bfloat16* __restrict__ Cbf,
        const float* __restrict__ att_s, const float* __restrict__ att_d,
        float* __restrict__ asrc, float* __restrict__ adst,
        float* __restrict__ sums_zero, float* __restrict__ sumsq_zero,
        const float* __restrict__ cin,
        const float* __restrict__ sums_rd, const float* __restrict__ sumsq_rd,
        const float* __restrict__ gamma, const float* __restrict__ beta,
        int heads, int M) {
    __shared__ unsigned As[128][33];
    __shared__ unsigned Bs[32][132];
    __shared__ float sa[128][2], sd[128][2];
    __shared__ float bnsc[128], bnsh[128];

    int tid = threadIdx.x;
    int wid = tid >> 5, lane = tid & 31;
    int wr = wid >> 1, wc = wid & 1;
    int g = lane >> 2, tg = lane & 3;
    int row0 = blockIdx.x * 128;

    if (att_s && blockIdx.x == 0 && tid < 128) {
        sums_zero[tid] = 0.f; sumsq_zero[tid] = 0.f;
    }
    if (cin) {
        if (tid < 128) {
            const float invN = 1.f / (float)NN;
            float mean = sums_rd[tid] * invN;
            float var = sumsq_rd[tid] * invN - mean * mean;
            float rs = rsqrtf(var + EPSB);
            float sc = rs * gamma[tid];
            bnsc[tid] = sc;
            bnsh[tid] = beta[tid] - mean * sc;
        }
        __syncthreads();
    }

    float acc[2][8][4];
    #pragma unroll
    for (int mt = 0; mt < 2; mt++)
        #pragma unroll
        for (int nt = 0; nt < 8; nt++)
            #pragma unroll
            for (int q = 0; q < 4; q++) acc[mt][nt][q] = 0.f;

    for (int kk = 0; kk < 128; kk += 32) {
        #pragma unroll
        for (int i = tid; i < 1024; i += 256) {
            int r = i >> 3, c = (i & 7) * 4;
            int col = kk + c;
            float4 v = make_float4(0.f, 0.f, 0.f, 0.f);
            if (row0 + r < M) {
                size_t off = (size_t)(row0 + r) * 128 + col;
                v = *(const float4*)(A + off);
                if (cin) {
                    float4 cv = *(const float4*)(cin + off);
                    v.x += fmaxf(cv.x * bnsc[col]     + bnsh[col],     0.f);
                    v.y += fmaxf(cv.y * bnsc[col + 1] + bnsh[col + 1], 0.f);
                    v.z += fmaxf(cv.z * bnsc[col + 2] + bnsh[col + 2], 0.f);
                    v.w += fmaxf(cv.w * bnsc[col + 3] + bnsh[col + 3], 0.f);
                    *(float4*)(A + off) = v;   // write updated h back
                }
            }
            As[r][c] = f2tf32(v.x); As[r][c + 1] = f2tf32(v.y);
            As[r][c + 2] = f2tf32(v.z); As[r][c + 3] = f2tf32(v.w);
        }
        #pragma unroll
        for (int i = tid; i < 1024; i += 256) {
            int kr = i >> 5, c = (i & 31) * 4;
            float4 v = *(const float4*)(B + (size_t)(kk + kr) * 128 + c);
            Bs[kr][c] = f2tf32(v.x); Bs[kr][c + 1] = f2tf32(v.y);
            Bs[kr][c + 2] = f2tf32(v.z); Bs[kr][c + 3] = f2tf32(v.w);
        }
        __syncthreads();
        #pragma unroll
        for (int ks = 0; ks < 4; ks++) {
            int k0 = ks * 8;
            unsigned a[2][4];
            #pragma unroll
            for (int mt = 0; mt < 2; mt++) {
                int rm = wr * 32 + mt * 16;
                a[mt][0] = As[rm + g][k0 + tg];
                a[mt][1] = As[rm + g + 8][k0 + tg];
                a[mt][2] = As[rm + g][k0 + tg + 4];
                a[mt][3] = As[rm + g + 8][k0 + tg + 4];
            }
            #pragma unroll
            for (int nt = 0; nt < 8; nt++) {
                int n0 = wc * 64 + nt * 8;
                unsigned b0 = Bs[k0 + tg][n0 + g];
                unsigned b1 = Bs[k0 + tg + 4][n0 + g];
                mma_tf32(acc[0][nt], a[0], b0, b1);
                mma_tf32(acc[1][nt], a[1], b0, b1);
            }
        }
        __syncthreads();
    }

    // ---- feature output ----
    #pragma unroll
    for (int mt = 0; mt < 2; mt++) {
        int ra = row0 + wr * 32 + mt * 16 + g;
        int rb = ra + 8;
        #pragma unroll
        for (int nt = 0; nt < 8; nt++) {
            int col = wc * 64 + nt * 8 + tg * 2;
            if (Cf32) {
                float b0v = bias ? bias[col] : 0.f;
                float b1v = bias ? bias[col + 1] : 0.f;
                if (ra < M) {
                    Cf32[(size_t)ra * 128 + col]     = acc[mt][nt][0] + b0v;
                    Cf32[(size_t)ra * 128 + col + 1] = acc[mt][nt][1] + b1v;
                }
                if (rb < M) {
                    Cf32[(size_t)rb * 128 + col]     = acc[mt][nt][2] + b0v;
                    Cf32[(size_t)rb * 128 + col + 1] = acc[mt][nt][3] + b1v;
                }
            }
            if (Cbf) {
                if (ra < M) {
                    __nv_bfloat162 p = __float22bfloat162_rn(
                        make_float2(acc[mt][nt][0], acc[mt][nt][1]));
                    *(__nv_bfloat162*)(Cbf + (size_t)ra * 128 + col) = p;
                }
                if (rb < M) {
                    __nv_bfloat162 p = __float22bfloat162_rn(
                        make_float2(acc[mt][nt][2], acc[mt][nt][3]));
                    *(__nv_bfloat162*)(Cbf + (size_t)rb * 128 + col) = p;
                }
            }
        }
    }

    // ---- fused attention coefficients ----
    if (att_s) {
        #pragma unroll
        for (int mt = 0; mt < 2; mt++) {
            float psa[4] = {0.f, 0.f, 0.f, 0.f}, psb[4] = {0.f, 0.f, 0.f, 0.f};
            float pda[4] = {0.f, 0.f, 0.f, 0.f}, pdb[4] = {0.f, 0.f, 0.f, 0.f};
            #pragma unroll
            for (int nt = 0; nt < 8; nt++) {
                int col = wc * 64 + nt * 8 + tg * 2;
                float ws0 = att_s[col], ws1 = att_s[col + 1];
                float wd0 = att_d[col], wd1 = att_d[col + 1];
                int b = nt >> 1;
                psa[b] += acc[mt][nt][0] * ws0 + acc[mt][nt][1] * ws1;
                psb[b] += acc[mt][nt][2] * ws0 + acc[mt][nt][3] * ws1;
                pda[b] += acc[mt][nt][0] * wd0 + acc[mt][nt][1] * wd1;
                pdb[b] += acc[mt][nt][2] * wd0 + acc[mt][nt][3] * wd1;
            }
            #pragma unroll
            for (int b = 0; b < 4; b++) {
                psa[b] += __shfl_xor_sync(0xffffffffu, psa[b], 1);
                psa[b] += __shfl_xor_sync(0xffffffffu, psa[b], 2);
                psb[b] += __shfl_xor_sync(0xffffffffu, psb[b], 1);
                psb[b] += __shfl_xor_sync(0xffffffffu, psb[b], 2);
                pda[b] += __shfl_xor_sync(0xffffffffu, pda[b], 1);
                pda[b] += __shfl_xor_sync(0xffffffffu, pda[b], 2);
                pdb[b] += __shfl_xor_sync(0xffffffffu, pdb[b], 1);
                pdb[b] += __shfl_xor_sync(0xffffffffu, pdb[b], 2);
            }
            int ra = row0 + wr * 32 + mt * 16 + g;
            int rb = ra + 8;
            if (heads == 8) {
                if (tg == 0) {
                    #pragma unroll
                    for (int b = 0; b < 4; b++) {
                        if (ra < M) {
                            asrc[ra * 8 + wc * 4 + b] = psa[b];
                            adst[ra * 8 + wc * 4 + b] = pda[b];
                        }
                        if (rb < M) {
                            asrc[rb * 8 + wc * 4 + b] = psb[b];
                            adst[rb * 8 + wc * 4 + b] = pdb[b];
                        }
                    }
                }
            } else {
                if (tg == 0) {
                    int la = wr * 32 + mt * 16 + g, lb = la + 8;
                    sa[la][wc] = psa[0] + psa[1] + psa[2] + psa[3];
                    sd[la][wc] = pda[0] + pda[1] + pda[2] + pda[3];
                    sa[lb][wc] = psb[0] + psb[1] + psb[2] + psb[3];
                    sd[lb][wc] = pdb[0] + pdb[1] + pdb[2] + pdb[3];
                }
            }
        }
        if (heads == 1) {
            __syncthreads();
            if (tid < 128) {
                int r = row0 + tid;
                if (r < M) {
                    asrc[r] = sa[tid][0] + sa[tid][1];
                    adst[r] = sd[tid][0] + sd[tid][1];
                }
            }
        }
    }
}

// ---------------- edge aggregation (warp/node, uint2, 4x unroll) ----------------
__global__ void agg_kernel(const __nv_bfloat16* __restrict__ featb,
                           const float* __restrict__ asrc,
                           const float* __restrict__ adst,
                           const int* __restrict__ rowptr,
                           const int* __restrict__ esrc,
                           float* __restrict__ cout,
                           float* __restrict__ sums,
                           float* __restrict__ sumsq,
                           int heads, int C) {
    __shared__ float ssum[128], ssq[128];
    int tid = threadIdx.x;
    if (tid < 128) { ssum[tid] = 0.f; ssq[tid] = 0.f; }
    __syncthreads();

    int warp = (blockIdx.x * blockDim.x + tid) >> 5;
    int lane = tid & 31;
    if (warp < NN) {
        int i = warp;
        int hd = (lane * 4) / C;
        float ad = adst[i * heads + hd];
        int beg = rowptr[i], end = rowptr[i + 1];
        const uint2* F = (const uint2*)featb;

        float den0 = 0.f, den1 = 0.f;
        float4 a0 = make_float4(0.f, 0.f, 0.f, 0.f);
        float4 a1 = make_float4(0.f, 0.f, 0.f, 0.f);
        int j = beg;
        for (; j + 3 < end; j += 4) {
            int s0 = esrc[j], s1 = esrc[j + 1], s2 = esrc[j + 2], s3 = esrc[j + 3];
            float v0 = asrc[s0 * heads + hd] + ad;
            float v1 = asrc[s1 * heads + hd] + ad;
            float v2 = asrc[s2 * heads + hd] + ad;
            float v3 = asrc[s3 * heads + hd] + ad;
            uint2 u0 = F[(size_t)s0 * 32 + lane];
            uint2 u1 = F[(size_t)s1 * 32 + lane];
            uint2 u2 = F[(size_t)s2 * 32 + lane];
            uint2 u3 = F[(size_t)s3 * 32 + lane];
            v0 = v0 > 0.f ? v0 : SLOPE * v0;
            v1 = v1 > 0.f ? v1 : SLOPE * v1;
            v2 = v2 > 0.f ? v2 : SLOPE * v2;
            v3 = v3 > 0.f ? v3 : SLOPE * v3;
            float w0 = __expf(v0), w1 = __expf(v1);
            float w2 = __expf(v2), w3 = __expf(v3);
            den0 += w0 + w2; den1 += w1 + w3;
            float2 f00 = __bfloat1622float2(*(__nv_bfloat162*)&u0.x);
            float2 f01 = __bfloat1622float2(*(__nv_bfloat162*)&u0.y);
            float2 f10 = __bfloat1622float2(*(__nv_bfloat162*)&u1.x);
            float2 f11 = __bfloat1622float2(*(__nv_bfloat162*)&u1.y);
            float2 f20 = __bfloat1622float2(*(__nv_bfloat162*)&u2.x);
            float2 f21 = __bfloat1622float2(*(__nv_bfloat162*)&u2.y);
            float2 f30 = __bfloat1622float2(*(__nv_bfloat162*)&u3.x);
            float2 f31 = __bfloat1622float2(*(__nv_bfloat162*)&u3.y);
            a0.x += f00.x * w0; a0.y += f00.y * w0; a0.z += f01.x * w0; a0.w += f01.y * w0;
            a1.x += f10.x * w1; a1.y += f10.y * w1; a1.z += f11.x * w1; a1.w += f11.y * w1;
            a0.x += f20.x * w2; a0.y += f20.y * w2; a0.z += f21.x * w2; a0.w += f21.y * w2;
            a1.x += f30.x * w3; a1.y += f30.y * w3; a1.z += f31.x * w3; a1.w += f31.y * w3;
        }
        for (; j < end; j++) {
            int s0 = esrc[j];
            float v0 = asrc[s0 * heads + hd] + ad;
            v0 = v0 > 0.f ? v0 : SLOPE * v0;
            float w0 = __expf(v0);
            uint2 u0 = F[(size_t)s0 * 32 + lane];
            float2 f00 = __bfloat1622float2(*(__nv_bfloat162*)&u0.x);
            float2 f01 = __bfloat1622float2(*(__nv_bfloat162*)&u0.y);
            den0 += w0;
            a0.x += f00.x * w0; a0.y += f00.y * w0; a0.z += f01.x * w0; a0.w += f01.y * w0;
        }
        float inv = 1.f / (den0 + den1);
        float4 o = make_float4((a0.x + a1.x) * inv, (a0.y + a1.y) * inv,
                               (a0.z + a1.z) * inv, (a0.w + a1.w) * inv);
        ((float4*)cout)[(size_t)i * 32 + lane] = o;

        int c0 = lane * 4;
        atomicAdd(&ssum[c0 + 0], o.x); atomicAdd(&ssq[c0 + 0], o.x * o.x);
        atomicAdd(&ssum[c0 + 1], o.y); atomicAdd(&ssq[c0 + 1], o.y * o.y);
        atomicAdd(&ssum[c0 + 2], o.z); atomicAdd(&ssq[c0 + 2], o.z * o.z);
        atomicAdd(&ssum[c0 + 3], o.w); atomicAdd(&ssq[c0 + 3], o.w * o.w);
    }
    __syncthreads();
    if (tid < 128) {
        atomicAdd(&sums[tid], ssum[tid]);
        atomicAdd(&sumsq[tid], ssq[tid]);
    }
}

// ---------------- fused final BN + pooling, full-chip parallel ----------------
// 128 threads/block, 64 nodes/block (~782 blocks). Per-graph partial sums
// accumulated locally, flushed at graph boundaries via atomicAdd.
#define NPB 64
__global__ __launch_bounds__(128) void bnpool_kernel(
        const float* __restrict__ h, const float* __restrict__ cin,
        const float* __restrict__ sums, const float* __restrict__ sumsq,
        const float* __restrict__ gamma, const float* __restrict__ beta,
        const int* __restrict__ batch, float* __restrict__ pooled) {
    __shared__ int sb[NPB];
    __shared__ float bnsc[128], bnsh[128];
    int tid = threadIdx.x;
    int r0 = blockIdx.x * NPB;
    int r1 = min(r0 + NPB, NN);
    {
        const float invN = 1.f / (float)NN;
        float mean = sums[tid] * invN;
        float var = sumsq[tid] * invN - mean * mean;
        float rs = rsqrtf(var + EPSB);
        float sc = rs * gamma[tid];
        bnsc[tid] = sc;
        bnsh[tid] = beta[tid] - mean * sc;
    }
    if (tid < r1 - r0) sb[tid] = batch[r0 + tid];
    __syncthreads();

    int c = tid;
    float sc = bnsc[c], sh = bnsh[c];
    float acc = 0.f;
    int cur = sb[0];
    for (int r = r0; r < r1; r++) {
        int g = sb[r - r0];
        if (g != cur) {
            atomicAdd(&pooled[cur * 128 + c], acc);
            acc = 0.f; cur = g;
        }
        float hv = h[(size_t)r * 128 + c];
        float cv = cin[(size_t)r * 128 + c];
        acc += hv + fmaxf(cv * sc + sh, 0.f);
    }
    atomicAdd(&pooled[cur * 128 + c], acc);
}

// ---------------- MLP head (divide by counts, then 3 layers) ----------------
__global__ __launch_bounds__(128) void mlp_kernel(
        const float* __restrict__ pooled, const int* __restrict__ batch,
        const float* __restrict__ W1, const float* __restrict__ b1,
        const float* __restrict__ W2, const float* __restrict__ b2,
        const float* __restrict__ W3, const float* __restrict__ b3,
        float* __restrict__ out) {
    __shared__ float p[128], t1[128], t2[128];
    int g = blockIdx.x, c = threadIdx.x;
    int a, b;
    {
        int lo = 0, hi = NN;
        while (lo < hi) { int mid = (lo + hi) >> 1; if (batch[mid] < g) lo = mid + 1; else hi = mid; }
        a = lo;
        lo = 0; hi = NN;
        int g1 = g + 1;
        while (lo < hi) { int mid = (lo + hi) >> 1; if (batch[mid] < g1) lo = mid + 1; else hi = mid; }
        b = lo;
    }
    float cnt = (float)(b - a);
    p[c] = pooled[g * 128 + c] / fmaxf(cnt, 1.f);
    __syncthreads();
    float s = b1[c];
    for (int k = 0; k < 128; k++) s += p[k] * W1[k * 128 + c];
    t1[c] = fmaxf(s, 0.f);
    __syncthreads();
    s = b2[c];
    for (int k = 0; k < 128; k++) s += t1[k] * W2[k * 128 + c];
    t2[c] = fmaxf(s, 0.f);
    __syncthreads();
    if (c < OUTD) {
        s = b3[c];
        for (int k = 0; k < 128; k++) s += t2[k] * W3[k * OUTD + c];
        out[g * OUTD + c] = s;
    }
}

// ---------------- launch ----------------
extern "C" void kernel_launch(void* const* d_in, const int* in_sizes, int n_in,
                              void* d_out, int out_size) {
    const float* x       = (const float*)d_in[0];
    const int*   ei      = (const int*)d_in[1];
    const int*   batch   = (const int*)d_in[3];
    const float* W_emb   = (const float*)d_in[4];
    const float* b_emb   = (const float*)d_in[5];
    const float* conv_W  = (const float*)d_in[6];
    const float* conv_as = (const float*)d_in[7];
    const float* conv_ad = (const float*)d_in[8];
    const float* conv2_W  = (const float*)d_in[10];
    const float* conv2_as = (const float*)d_in[11];
    const float* conv2_ad = (const float*)d_in[12];
    const float* bn_gamma = (const float*)d_in[14];
    const float* bn_beta  = (const float*)d_in[15];
    const float* lin1_W   = (const float*)d_in[16];
    const float* lin1_b   = (const float*)d_in[17];
    const float* lin2_W   = (const float*)d_in[18];
    const float* lin2_b   = (const float*)d_in[19];
    const float* lin3_W   = (const float*)d_in[20];
    const float* lin3_b   = (const float*)d_in[21];
    float* out = (float*)d_out;

    float *p_h, *p_c, *p_asrc, *p_adst, *p_sums, *p_sumsq, *p_pooled;
    __nv_bfloat16* p_featb;
    int *p_deg, *p_cursor, *p_rowptr, *p_esrc;
    cudaGetSymbolAddress((void**)&p_h,      g_h);
    cudaGetSymbolAddress((void**)&p_featb,  g_featb);
    cudaGetSymbolAddress((void**)&p_c,      g_c);
    cudaGetSymbolAddress((void**)&p_asrc,   g_asrc);
    cudaGetSymbolAddress((void**)&p_adst,   g_adst);
    cudaGetSymbolAddress((void**)&p_sums,   g_sums);
    cudaGetSymbolAddress((void**)&p_sumsq,  g_sumsq);
    cudaGetSymbolAddress((void**)&p_pooled, g_pooled);
    cudaGetSymbolAddress((void**)&p_deg,    g_deg);
    cudaGetSymbolAddress((void**)&p_cursor, g_cursor);
    cudaGetSymbolAddress((void**)&p_rowptr, g_rowptr);
    cudaGetSymbolAddress((void**)&p_esrc,   g_esrc);

    const int E = in_sizes[1] / 2;
    const int et = E + NN;
    const int gblocks = (NN + 127) / 128;

    zero_deg_kernel<<<(NN + 255) / 256, 256>>>(p_deg, p_pooled);
    hist_kernel<<<(et + 255) / 256, 256>>>(ei, E, p_deg);
    scan_kernel<<<1, 1024>>>(p_deg, p_rowptr, p_cursor);
    scatter_kernel<<<(et + 255) / 256, 256>>>(ei, E, p_cursor, p_esrc);

    // embedding: fp32 output + bias; no att, no BN fusion
    gemm_tc_kernel<<<gblocks, 256>>>((float*)x, W_emb, b_emb, p_h, nullptr,
                                     nullptr, nullptr, nullptr, nullptr,
                                     nullptr, nullptr,
                                     nullptr, nullptr, nullptr, nullptr, nullptr,
                                     0, NN);

    for (int layer = 0; layer < 3; layer++) {
        const float* W  = (layer < 2) ? conv_W  + (size_t)layer * 128 * 128 : conv2_W;
        const float* as = (layer < 2) ? conv_as + (size_t)layer * 128      : conv2_as;
        const float* ad = (layer < 2) ? conv_ad + (size_t)layer * 128      : conv2_ad;
        int heads = (layer < 2) ? 8 : 1;
        int C     = (layer < 2) ? 16 : 128;
        int bw = layer & 1;            // stats buffer this layer's agg writes
        int br = (layer - 1) & 1;      // stats buffer previous agg wrote

        gemm_tc_kernel<<<gblocks, 256>>>(
            p_h, W, nullptr, nullptr, p_featb,
            as, ad, p_asrc, p_adst,
            p_sums + bw * 128, p_sumsq + bw * 128,
            (layer > 0) ? p_c : nullptr,
            p_sums + br * 128, p_sumsq + br * 128,
            bn_gamma + (layer - 1) * 128, bn_beta + (layer - 1) * 128,
            heads, NN);

        agg_kernel<<<(NN * 32 + 255) / 256, 256>>>(p_featb, p_asrc, p_adst,
                                                   p_rowptr, p_esrc, p_c,
                                                   p_sums + bw * 128,
                                                   p_sumsq + bw * 128, heads, C);
    }

    // fused final BN (layer2 stats, buffer 0) + pooling (full-chip), then MLP
    bnpool_kernel<<<(NN + NPB - 1) / NPB, 128>>>(p_h, p_c, p_sums, p_sumsq,
                                                 bn_gamma + 2 * 128,
                                                 bn_beta + 2 * 128,
                                                 batch, p_pooled);
    mlp_kernel<<<GG, 128>>>(p_pooled, batch,
                            lin1_W, lin1_b, lin2_W, lin2_b, lin3_W, lin3_b, out);
}

// round 13
// speedup vs baseline: 1.5777x; 1.5777x over previous
#include <cuda_runtime.h>
#include <cuda_bf16.h>

#define NN 50000
#define EE 800000
#define ET (EE + NN)
#define HID 128
#define GG 64
#define OUTD 10
#define SLOPE 0.2f
#define EPSB 1e-5f

// ---------------- static scratch ----------------
__device__ __align__(16) float g_h[NN * HID];
__device__ __align__(16) __nv_bfloat16 g_featb[NN * HID];
__device__ __align__(16) float g_c[NN * HID];
__device__ float g_asrc[NN * 8];
__device__ float g_adst[NN * 8];
__device__ int   g_deg[NN];
__device__ int   g_cursor[NN];
__device__ int   g_rowptr[NN + 1];
__device__ int   g_esrc[ET];
__device__ float g_sums[2 * HID];    // double-buffered BN stats
__device__ float g_sumsq[2 * HID];
__device__ int   g_starts[GG + 1];
__device__ float g_pooled[GG * HID];

// ---------------- CSR build ----------------
__global__ void zero_counts_kernel(int* deg, int* cursor) {
    int i = blockIdx.x * blockDim.x + threadIdx.x;
    if (i < NN) { deg[i] = 0; cursor[i] = 0; }
}

__global__ void hist_kernel(const int* __restrict__ ei, int E, int* deg) {
    int e = blockIdx.x * blockDim.x + threadIdx.x;
    if (e >= E + NN) return;
    int dst = (e < E) ? ei[E + e] : (e - E);
    atomicAdd(&deg[dst], 1);
}

__global__ void scan_kernel(const int* __restrict__ deg, int* __restrict__ rowptr) {
    __shared__ int s[1024];
    const int T = 1024;
    int tid = threadIdx.x;
    int chunk = (NN + T - 1) / T;
    int start = tid * chunk;
    int sum = 0;
    for (int i = 0; i < chunk; i++) {
        int idx = start + i;
        if (idx < NN) sum += deg[idx];
    }
    s[tid] = sum;
    __syncthreads();
    for (int off = 1; off < T; off <<= 1) {
        int v = (tid >= off) ? s[tid - off] : 0;
        __syncthreads();
        s[tid] += v;
        __syncthreads();
    }
    int run = (tid == 0) ? 0 : s[tid - 1];
    for (int i = 0; i < chunk; i++) {
        int idx = start + i;
        if (idx < NN) { rowptr[idx] = run; run += deg[idx]; }
    }
    if (tid == T - 1) rowptr[NN] = s[T - 1];
}

__global__ void scatter_kernel(const int* __restrict__ ei, int E,
                               const int* __restrict__ rowptr,
                               int* __restrict__ cursor,
                               int* __restrict__ esrc) {
    int e = blockIdx.x * blockDim.x + threadIdx.x;
    if (e >= E + NN) return;
    int src, dst;
    if (e < E) { src = ei[e]; dst = ei[E + e]; }
    else       { src = e - E; dst = e - E; }
    int pos = rowptr[dst] + atomicAdd(&cursor[dst], 1);
    esrc[pos] = src;
}

// ---------------- tf32 helpers ----------------
__device__ __forceinline__ unsigned f2tf32(float f) {
    unsigned u;
    asm("cvt.rna.tf32.f32 %0, %1;" : "=r"(u) : "f"(f));
    return u;
}

__device__ __forceinline__ void mma_tf32(float* d, const unsigned* a,
                                         unsigned b0, unsigned b1) {
    asm volatile(
        "mma.sync.aligned.m16n8k8.row.col.f32.tf32.tf32.f32 "
        "{%0,%1,%2,%3},{%4,%5,%6,%7},{%8,%9},{%0,%1,%2,%3};"
        : "+f"(d[0]), "+f"(d[1]), "+f"(d[2]), "+f"(d[3])
        : "r"(a[0]), "r"(a[1]), "r"(a[2]), "r"(a[3]), "r"(b0), "r"(b1));
}

// ---------------- tensor-core GEMM, fused: BN-prologue + attention epilogue ----
__global__ __launch_bounds__(256) void gemm_tc_kernel(
        float* __restrict__ A, const float* __restrict__ B,
        const float* __restrict__ bias,
        float* __restrict__ Cf32, __nv_bfloat16* __restrict__ Cbf,
        const float* __restrict__ att_s, const float* __restrict__ att_d,
        float* __restrict__ asrc, float* __restrict__ adst,
        float* __restrict__ sums_zero, float* __restrict__ sumsq_zero,
        const float* __restrict__ cin,
        const float* __restrict__ sums_rd, const float* __restrict__ sumsq_rd,
        const float* __restrict__ gamma, const float* __restrict__ beta,
        int heads, int M) {
    __shared__ unsigned As[128][33];
    __shared__ unsigned Bs[32][132];
    __shared__ float sa[128][2], sd[128][2];
    __shared__ float bnsc[128], bnsh[128];

    int tid = threadIdx.x;
    int wid = tid >> 5, lane = tid & 31;
    int wr = wid >> 1, wc = wid & 1;
    int g = lane >> 2, tg = lane & 3;
    int row0 = blockIdx.x * 128;

    if (att_s && blockIdx.x == 0 && tid < 128) {
        sums_zero[tid] = 0.f; sumsq_zero[tid] = 0.f;
    }
    if (cin) {
        if (tid < 128) {
            const float invN = 1.f / (float)NN;
            float mean = sums_rd[tid] * invN;
            float var = sumsq_rd[tid] * invN - mean * mean;
            float rs = rsqrtf(var + EPSB);
            float sc = rs * gamma[tid];
            bnsc[tid] = sc;
            bnsh[tid] = beta[tid] - mean * sc;
        }
        __syncthreads();
    }

    float acc[2][8][4];
    #pragma unroll
    for (int mt = 0; mt < 2; mt++)
        #pragma unroll
        for (int nt = 0; nt < 8; nt++)
            #pragma unroll
            for (int q = 0; q < 4; q++) acc[mt][nt][q] = 0.f;

    for (int kk = 0; kk < 128; kk += 32) {
        #pragma unroll
        for (int i = tid; i < 1024; i += 256) {
            int r = i >> 3, c = (i & 7) * 4;
            int col = kk + c;
            float4 v = make_float4(0.f, 0.f, 0.f, 0.f);
            if (row0 + r < M) {
                size_t off = (size_t)(row0 + r) * 128 + col;
                v = *(const float4*)(A + off);
                if (cin) {
                    float4 cv = *(const float4*)(cin + off);
                    v.x += fmaxf(cv.x * bnsc[col]     + bnsh[col],     0.f);
                    v.y += fmaxf(cv.y * bnsc[col + 1] + bnsh[col + 1], 0.f);
                    v.z += fmaxf(cv.z * bnsc[col + 2] + bnsh[col + 2], 0.f);
                    v.w += fmaxf(cv.w * bnsc[col + 3] + bnsh[col + 3], 0.f);
                    *(float4*)(A + off) = v;   // write updated h back
                }
            }
            As[r][c] = f2tf32(v.x); As[r][c + 1] = f2tf32(v.y);
            As[r][c + 2] = f2tf32(v.z); As[r][c + 3] = f2tf32(v.w);
        }
        #pragma unroll
        for (int i = tid; i < 1024; i += 256) {
            int kr = i >> 5, c = (i & 31) * 4;
            float4 v = *(const float4*)(B + (size_t)(kk + kr) * 128 + c);
            Bs[kr][c] = f2tf32(v.x); Bs[kr][c + 1] = f2tf32(v.y);
            Bs[kr][c + 2] = f2tf32(v.z); Bs[kr][c + 3] = f2tf32(v.w);
        }
        __syncthreads();
        #pragma unroll
        for (int ks = 0; ks < 4; ks++) {
            int k0 = ks * 8;
            unsigned a[2][4];
            #pragma unroll
            for (int mt = 0; mt < 2; mt++) {
                int rm = wr * 32 + mt * 16;
                a[mt][0] = As[rm + g][k0 + tg];
                a[mt][1] = As[rm + g + 8][k0 + tg];
                a[mt][2] = As[rm + g][k0 + tg + 4];
                a[mt][3] = As[rm + g + 8][k0 + tg + 4];
            }
            #pragma unroll
            for (int nt = 0; nt < 8; nt++) {
                int n0 = wc * 64 + nt * 8;
                unsigned b0 = Bs[k0 + tg][n0 + g];
                unsigned b1 = Bs[k0 + tg + 4][n0 + g];
                mma_tf32(acc[0][nt], a[0], b0, b1);
                mma_tf32(acc[1][nt], a[1], b0, b1);
            }
        }
        __syncthreads();
    }

    // ---- feature output ----
    #pragma unroll
    for (int mt = 0; mt < 2; mt++) {
        int ra = row0 + wr * 32 + mt * 16 + g;
        int rb = ra + 8;
        #pragma unroll
        for (int nt = 0; nt < 8; nt++) {
            int col = wc * 64 + nt * 8 + tg * 2;
            if (Cf32) {
                float b0v = bias ? bias[col] : 0.f;
                float b1v = bias ? bias[col + 1] : 0.f;
                if (ra < M) {
                    Cf32[(size_t)ra * 128 + col]     = acc[mt][nt][0] + b0v;
                    Cf32[(size_t)ra * 128 + col + 1] = acc[mt][nt][1] + b1v;
                }
                if (rb < M) {
                    Cf32[(size_t)rb * 128 + col]     = acc[mt][nt][2] + b0v;
                    Cf32[(size_t)rb * 128 + col + 1] = acc[mt][nt][3] + b1v;
                }
            }
            if (Cbf) {
                if (ra < M) {
                    __nv_bfloat162 p = __float22bfloat162_rn(
                        make_float2(acc[mt][nt][0], acc[mt][nt][1]));
                    *(__nv_bfloat162*)(Cbf + (size_t)ra * 128 + col) = p;
                }
                if (rb < M) {
                    __nv_bfloat162 p = __float22bfloat162_rn(
                        make_float2(acc[mt][nt][2], acc[mt][nt][3]));
                    *(__nv_bfloat162*)(Cbf + (size_t)rb * 128 + col) = p;
                }
            }
        }
    }

    // ---- fused attention coefficients ----
    if (att_s) {
        #pragma unroll
        for (int mt = 0; mt < 2; mt++) {
            float psa[4] = {0.f, 0.f, 0.f, 0.f}, psb[4] = {0.f, 0.f, 0.f, 0.f};
            float pda[4] = {0.f, 0.f, 0.f, 0.f}, pdb[4] = {0.f, 0.f, 0.f, 0.f};
            #pragma unroll
            for (int nt = 0; nt < 8; nt++) {
                int col = wc * 64 + nt * 8 + tg * 2;
                float ws0 = att_s[col], ws1 = att_s[col + 1];
                float wd0 = att_d[col], wd1 = att_d[col + 1];
                int b = nt >> 1;
                psa[b] += acc[mt][nt][0] * ws0 + acc[mt][nt][1] * ws1;
                psb[b] += acc[mt][nt][2] * ws0 + acc[mt][nt][3] * ws1;
                pda[b] += acc[mt][nt][0] * wd0 + acc[mt][nt][1] * wd1;
                pdb[b] += acc[mt][nt][2] * wd0 + acc[mt][nt][3] * wd1;
            }
            #pragma unroll
            for (int b = 0; b < 4; b++) {
                psa[b] += __shfl_xor_sync(0xffffffffu, psa[b], 1);
                psa[b] += __shfl_xor_sync(0xffffffffu, psa[b], 2);
                psb[b] += __shfl_xor_sync(0xffffffffu, psb[b], 1);
                psb[b] += __shfl_xor_sync(0xffffffffu, psb[b], 2);
                pda[b] += __shfl_xor_sync(0xffffffffu, pda[b], 1);
                pda[b] += __shfl_xor_sync(0xffffffffu, pda[b], 2);
                pdb[b] += __shfl_xor_sync(0xffffffffu, pdb[b], 1);
                pdb[b] += __shfl_xor_sync(0xffffffffu, pdb[b], 2);
            }
            int ra = row0 + wr * 32 + mt * 16 + g;
            int rb = ra + 8;
            if (heads == 8) {
                if (tg == 0) {
                    #pragma unroll
                    for (int b = 0; b < 4; b++) {
                        if (ra < M) {
                            asrc[ra * 8 + wc * 4 + b] = psa[b];
                            adst[ra * 8 + wc * 4 + b] = pda[b];
                        }
                        if (rb < M) {
                            asrc[rb * 8 + wc * 4 + b] = psb[b];
                            adst[rb * 8 + wc * 4 + b] = pdb[b];
                        }
                    }
                }
            } else {
                if (tg == 0) {
                    int la = wr * 32 + mt * 16 + g, lb = la + 8;
                    sa[la][wc] = psa[0] + psa[1] + psa[2] + psa[3];
                    sd[la][wc] = pda[0] + pda[1] + pda[2] + pda[3];
                    sa[lb][wc] = psb[0] + psb[1] + psb[2] + psb[3];
                    sd[lb][wc] = pdb[0] + pdb[1] + pdb[2] + pdb[3];
                }
            }
        }
        if (heads == 1) {
            __syncthreads();
            if (tid < 128) {
                int r = row0 + tid;
                if (r < M) {
                    asrc[r] = sa[tid][0] + sa[tid][1];
                    adst[r] = sd[tid][0] + sd[tid][1];
                }
            }
        }
    }
}

// ---------------- edge aggregation (warp/node, uint2, 4x unroll) ----------------
__global__ void agg_kernel(const __nv_bfloat16* __restrict__ featb,
                           const float* __restrict__ asrc,
                           const float* __restrict__ adst,
                           const int* __restrict__ rowptr,
                           const int* __restrict__ esrc,
                           float* __restrict__ cout,
                           float* __restrict__ sums,
                           float* __restrict__ sumsq,
                           int heads, int C) {
    __shared__ float ssum[128], ssq[128];
    int tid = threadIdx.x;
    if (tid < 128) { ssum[tid] = 0.f; ssq[tid] = 0.f; }
    __syncthreads();

    int warp = (blockIdx.x * blockDim.x + tid) >> 5;
    int lane = tid & 31;
    if (warp < NN) {
        int i = warp;
        int hd = (lane * 4) / C;
        float ad = adst[i * heads + hd];
        int beg = rowptr[i], end = rowptr[i + 1];
        const uint2* F = (const uint2*)featb;

        float den0 = 0.f, den1 = 0.f;
        float4 a0 = make_float4(0.f, 0.f, 0.f, 0.f);
        float4 a1 = make_float4(0.f, 0.f, 0.f, 0.f);
        int j = beg;
        for (; j + 3 < end; j += 4) {
            int s0 = esrc[j], s1 = esrc[j + 1], s2 = esrc[j + 2], s3 = esrc[j + 3];
            float v0 = asrc[s0 * heads + hd] + ad;
            float v1 = asrc[s1 * heads + hd] + ad;
            float v2 = asrc[s2 * heads + hd] + ad;
            float v3 = asrc[s3 * heads + hd] + ad;
            uint2 u0 = F[(size_t)s0 * 32 + lane];
            uint2 u1 = F[(size_t)s1 * 32 + lane];
            uint2 u2 = F[(size_t)s2 * 32 + lane];
            uint2 u3 = F[(size_t)s3 * 32 + lane];
            v0 = v0 > 0.f ? v0 : SLOPE * v0;
            v1 = v1 > 0.f ? v1 : SLOPE * v1;
            v2 = v2 > 0.f ? v2 : SLOPE * v2;
            v3 = v3 > 0.f ? v3 : SLOPE * v3;
            float w0 = __expf(v0), w1 = __expf(v1);
            float w2 = __expf(v2), w3 = __expf(v3);
            den0 += w0 + w2; den1 += w1 + w3;
            float2 f00 = __bfloat1622float2(*(__nv_bfloat162*)&u0.x);
            float2 f01 = __bfloat1622float2(*(__nv_bfloat162*)&u0.y);
            float2 f10 = __bfloat1622float2(*(__nv_bfloat162*)&u1.x);
            float2 f11 = __bfloat1622float2(*(__nv_bfloat162*)&u1.y);
            float2 f20 = __bfloat1622float2(*(__nv_bfloat162*)&u2.x);
            float2 f21 = __bfloat1622float2(*(__nv_bfloat162*)&u2.y);
            float2 f30 = __bfloat1622float2(*(__nv_bfloat162*)&u3.x);
            float2 f31 = __bfloat1622float2(*(__nv_bfloat162*)&u3.y);
            a0.x += f00.x * w0; a0.y += f00.y * w0; a0.z += f01.x * w0; a0.w += f01.y * w0;
            a1.x += f10.x * w1; a1.y += f10.y * w1; a1.z += f11.x * w1; a1.w += f11.y * w1;
            a0.x += f20.x * w2; a0.y += f20.y * w2; a0.z += f21.x * w2; a0.w += f21.y * w2;
            a1.x += f30.x * w3; a1.y += f30.y * w3; a1.z += f31.x * w3; a1.w += f31.y * w3;
        }
        for (; j < end; j++) {
            int s0 = esrc[j];
            float v0 = asrc[s0 * heads + hd] + ad;
            v0 = v0 > 0.f ? v0 : SLOPE * v0;
            float w0 = __expf(v0);
            uint2 u0 = F[(size_t)s0 * 32 + lane];
            float2 f00 = __bfloat1622float2(*(__nv_bfloat162*)&u0.x);
            float2 f01 = __bfloat1622float2(*(__nv_bfloat162*)&u0.y);
            den0 += w0;
            a0.x += f00.x * w0; a0.y += f00.y * w0; a0.z += f01.x * w0; a0.w += f01.y * w0;
        }
        float inv = 1.f / (den0 + den1);
        float4 o = make_float4((a0.x + a1.x) * inv, (a0.y + a1.y) * inv,
                               (a0.z + a1.z) * inv, (a0.w + a1.w) * inv);
        ((float4*)cout)[(size_t)i * 32 + lane] = o;

        int c0 = lane * 4;
        atomicAdd(&ssum[c0 + 0], o.x); atomicAdd(&ssq[c0 + 0], o.x * o.x);
        atomicAdd(&ssum[c0 + 1], o.y); atomicAdd(&ssq[c0 + 1], o.y * o.y);
        atomicAdd(&ssum[c0 + 2], o.z); atomicAdd(&ssq[c0 + 2], o.z * o.z);
        atomicAdd(&ssum[c0 + 3], o.w); atomicAdd(&ssq[c0 + 3], o.w * o.w);
    }
    __syncthreads();
    if (tid < 128) {
        atomicAdd(&sums[tid], ssum[tid]);
        atomicAdd(&sumsq[tid], ssq[tid]);
    }
}

// ---------------- BatchNorm apply + ReLU + residual (final layer only) --------
// Per-channel scale/shift computed ONCE per block in shared (kills the 6.4M
// per-element rsqrtf MUFU bottleneck).
__global__ __launch_bounds__(256) void bn_apply_kernel(
        const float* __restrict__ cin,
        const float* __restrict__ sums,
        const float* __restrict__ sumsq,
        const float* __restrict__ gamma,
        const float* __restrict__ beta,
        float* __restrict__ h) {
    __shared__ float bnsc[128], bnsh[128];
    int tid = threadIdx.x;
    if (tid < 128) {
        const float invN = 1.f / (float)NN;
        float mean = sums[tid] * invN;
        float var = sumsq[tid] * invN - mean * mean;
        float rs = rsqrtf(var + EPSB);
        float sc = rs * gamma[tid];
        bnsc[tid] = sc;
        bnsh[tid] = beta[tid] - mean * sc;
    }
    __syncthreads();
    int idx = blockIdx.x * blockDim.x + tid;   // one float4 each
    if (idx >= NN * 32) return;
    int c0 = (idx & 31) * 4;
    float4 cv = ((const float4*)cin)[idx];
    float4 hv = ((const float4*)h)[idx];
    hv.x += fmaxf(cv.x * bnsc[c0]     + bnsh[c0],     0.f);
    hv.y += fmaxf(cv.y * bnsc[c0 + 1] + bnsh[c0 + 1], 0.f);
    hv.z += fmaxf(cv.z * bnsc[c0 + 2] + bnsh[c0 + 2], 0.f);
    hv.w += fmaxf(cv.w * bnsc[c0 + 3] + bnsh[c0 + 3], 0.f);
    ((float4*)h)[idx] = hv;
}

// ---------------- pooling ----------------
__global__ void bounds_kernel(const int* __restrict__ batch, int* __restrict__ starts) {
    int g = threadIdx.x;
    if (g > GG) return;
    if (g == GG) { starts[GG] = NN; return; }
    int lo = 0, hi = NN;
    while (lo < hi) {
        int mid = (lo + hi) >> 1;
        if (batch[mid] < g) lo = mid + 1; else hi = mid;
    }
    starts[g] = lo;
}

__global__ void pool_kernel(const float* __restrict__ h,
                            const int* __restrict__ starts,
                            float* __restrict__ pooled) {
    __shared__ float red[512];
    int g = blockIdx.x;
    int c = threadIdx.x & 127;
    int seg = threadIdx.x >> 7;
    int a = starts[g], b = starts[g + 1];
    float s = 0.f;
    for (int r = a + seg; r < b; r += 4) s += h[(size_t)r * 128 + c];
    red[threadIdx.x] = s;
    __syncthreads();
    if (seg == 0) {
        float t = red[c] + red[c + 128] + red[c + 256] + red[c + 384];
        float cnt = (float)(b - a);
        pooled[g * 128 + c] = t / fmaxf(cnt, 1.f);
    }
}

// ---------------- MLP head ----------------
__global__ void mlp_kernel(const float* __restrict__ pooled,
                           const float* __restrict__ W1, const float* __restrict__ b1,
                           const float* __restrict__ W2, const float* __restrict__ b2,
                           const float* __restrict__ W3, const float* __restrict__ b3,
                           float* __restrict__ out) {
    __shared__ float p[128], t1[128], t2[128];
    int g = blockIdx.x, c = threadIdx.x;
    p[c] = pooled[g * 128 + c];
    __syncthreads();
    float s = b1[c];
    for (int k = 0; k < 128; k++) s += p[k] * W1[k * 128 + c];
    t1[c] = fmaxf(s, 0.f);
    __syncthreads();
    s = b2[c];
    for (int k = 0; k < 128; k++) s += t1[k] * W2[k * 128 + c];
    t2[c] = fmaxf(s, 0.f);
    __syncthreads();
    if (c < OUTD) {
        s = b3[c];
        for (int k = 0; k < 128; k++) s += t2[k] * W3[k * OUTD + c];
        out[g * OUTD + c] = s;
    }
}

// ---------------- launch ----------------
extern "C" void kernel_launch(void* const* d_in, const int* in_sizes, int n_in,
                              void* d_out, int out_size) {
    const float* x       = (const float*)d_in[0];
    const int*   ei      = (const int*)d_in[1];
    const int*   batch   = (const int*)d_in[3];
    const float* W_emb   = (const float*)d_in[4];
    const float* b_emb   = (const float*)d_in[5];
    const float* conv_W  = (const float*)d_in[6];
    const float* conv_as = (const float*)d_in[7];
    const float* conv_ad = (const float*)d_in[8];
    const float* conv2_W  = (const float*)d_in[10];
    const float* conv2_as = (const float*)d_in[11];
    const float* conv2_ad = (const float*)d_in[12];
    const float* bn_gamma = (const float*)d_in[14];
    const float* bn_beta  = (const float*)d_in[15];
    const float* lin1_W   = (const float*)d_in[16];
    const float* lin1_b   = (const float*)d_in[17];
    const float* lin2_W   = (const float*)d_in[18];
    const float* lin2_b   = (const float*)d_in[19];
    const float* lin3_W   = (const float*)d_in[20];
    const float* lin3_b   = (const float*)d_in[21];
    float* out = (float*)d_out;

    float *p_h, *p_c, *p_asrc, *p_adst, *p_sums, *p_sumsq, *p_pooled;
    __nv_bfloat16* p_featb;
    int *p_deg, *p_cursor, *p_rowptr, *p_esrc, *p_starts;
    cudaGetSymbolAddress((void**)&p_h,      g_h);
    cudaGetSymbolAddress((void**)&p_featb,  g_featb);
    cudaGetSymbolAddress((void**)&p_c,      g_c);
    cudaGetSymbolAddress((void**)&p_asrc,   g_asrc);
    cudaGetSymbolAddress((void**)&p_adst,   g_adst);
    cudaGetSymbolAddress((void**)&p_sums,   g_sums);
    cudaGetSymbolAddress((void**)&p_sumsq,  g_sumsq);
    cudaGetSymbolAddress((void**)&p_pooled, g_pooled);
    cudaGetSymbolAddress((void**)&p_deg,    g_deg);
    cudaGetSymbolAddress((void**)&p_cursor, g_cursor);
    cudaGetSymbolAddress((void**)&p_rowptr, g_rowptr);
    cudaGetSymbolAddress((void**)&p_esrc,   g_esrc);
    cudaGetSymbolAddress((void**)&p_starts, g_starts);

    const int E = in_sizes[1] / 2;
    const int et = E + NN;
    const int gblocks = (NN + 127) / 128;

    zero_counts_kernel<<<(NN + 255) / 256, 256>>>(p_deg, p_cursor);
    hist_kernel<<<(et + 255) / 256, 256>>>(ei, E, p_deg);
    scan_kernel<<<1, 1024>>>(p_deg, p_rowptr);
    scatter_kernel<<<(et + 255) / 256, 256>>>(ei, E, p_rowptr, p_cursor, p_esrc);

    // embedding: fp32 output + bias; no att, no BN fusion
    gemm_tc_kernel<<<gblocks, 256>>>((float*)x, W_emb, b_emb, p_h, nullptr,
                                     nullptr, nullptr, nullptr, nullptr,
                                     nullptr, nullptr,
                                     nullptr, nullptr, nullptr, nullptr, nullptr,
                                     0, NN);

    for (int layer = 0; layer < 3; layer++) {
        const float* W  = (layer < 2) ? conv_W  + (size_t)layer * 128 * 128 : conv2_W;
        const float* as = (layer < 2) ? conv_as + (size_t)layer * 128      : conv2_as;
        const float* ad = (layer < 2) ? conv_ad + (size_t)layer * 128      : conv2_ad;
        int heads = (layer < 2) ? 8 : 1;
        int C     = (layer < 2) ? 16 : 128;
        int bw = layer & 1;            // stats buffer this layer's agg writes
        int br = (layer - 1) & 1;      // stats buffer previous agg wrote

        gemm_tc_kernel<<<gblocks, 256>>>(
            p_h, W, nullptr, nullptr, p_featb,
            as, ad, p_asrc, p_adst,
            p_sums + bw * 128, p_sumsq + bw * 128,
            (layer > 0) ? p_c : nullptr,
            p_sums + br * 128, p_sumsq + br * 128,
            bn_gamma + (layer - 1) * 128, bn_beta + (layer - 1) * 128,
            heads, NN);

        agg_kernel<<<(NN * 32 + 255) / 256, 256>>>(p_featb, p_asrc, p_adst,
                                                   p_rowptr, p_esrc, p_c,
                                                   p_sums + bw * 128,
                                                   p_sumsq + bw * 128, heads, C);
    }

    // final BN+ReLU+residual (layer 2 stats live in buffer 0)
    bn_apply_kernel<<<(NN * 32 + 255) / 256, 256>>>(p_c, p_sums, p_sumsq,
                                                    bn_gamma + 2 * 128,
                                                    bn_beta + 2 * 128, p_h);

    bounds_kernel<<<1, 128>>>(batch, p_starts);
    pool_kernel<<<GG, 512>>>(p_h, p_starts, p_pooled);
    mlp_kernel<<<GG, 128>>>(p_pooled, lin1_W, lin1_b, lin2_W, lin2_b, lin3_W, lin3_b, out);
}